// round 8
// baseline (speedup 1.0000x reference)
#include <cuda_runtime.h>

// ---------------------------------------------------------------------------
// HGT layer, round 6: sub-bucketed counting sort (kills ATOMG serialization
// on the 50-node topic dst cursors), otherwise round-4 pipeline.
//
//   K0 zero   : g_w, g_den, g_cnt; transpose msg -> g_msgT [e][dd][h][f]
//   K1 hist   : per-edge histogram over expanded (etype,dst,sub) buckets
//   K2 scan   : exclusive prefix sum over 130400 bucket counters (1 block)
//   K3 scatter: sorted edge records rec = (slot<<15)|src_global (u32)
//   K4 proj   : kqv projection GEMM (f32x2 packed FMA)
//   K5 accum  : warp per 64-edge chunk; register accumulation per run;
//               red.v4 flush per run
//   K6 out    : coalesced w-row float4 + shfl + transposed msg float4,
//               relu + mean cross-reduce + LayerNorm
// ---------------------------------------------------------------------------

#define E_PER  150000
#define E_TOT  1200000
#define NNODE  22050
#define WTOT   64150
#define WEXT   130400   // expanded (slot,sub) bucket count
#define CH     64
#define NCHUNK (E_TOT / CH)   // 18750

__device__ float    g_k[NNODE * 128];
__device__ float    g_q[NNODE * 128];
__device__ float    g_v[NNODE * 128];
__device__ float    g_w[(size_t)WTOT * 128];
__device__ float    g_den[(size_t)WTOT * 8];
__device__ int      g_cnt[WEXT];
__device__ int      g_pos[WEXT];
__device__ unsigned g_rec[E_TOT];
__device__ float    g_msgT[8 * 16 * 8 * 16];   // [e][dd][h][f]

__constant__ int   c_off[3]    = {0, 20000, 20050};
__constant__ int   c_nt[3]     = {20000, 50, 2000};
__constant__ int   c_src_t[8]  = {0, 0, 1, 1, 0, 1, 2, 2};
__constant__ int   c_dst_t[8]  = {1, 2, 2, 1, 0, 0, 1, 0};
__constant__ int   c_woff[8]   = {0, 50, 2050, 4050, 4100, 24100, 44100, 44150};
// expanded bucket layout: topic-dst etypes get 256 sub-buckets/slot,
// doc-dst 8, word-dst 1 (contention-proportional)
__constant__ int   c_exoff[8]  = {0, 12800, 28800, 44800, 57600, 77600, 97600, 110400};
__constant__ int   c_subsh[8]  = {8, 3, 3, 8, 0, 0, 8, 0};
__constant__ int   c_t2e[3][3] = {{4, 5, 7}, {0, 3, 6}, {1, 2, -1}};
__constant__ float c_invcnt[3] = {1.0f / 3.0f, 1.0f / 3.0f, 0.5f};

// ---------------------------------------------------------------------------
// K0: zero accumulators + counters; build transposed msg copy.
// ---------------------------------------------------------------------------
__global__ void zero_kernel(const float* __restrict__ msg)
{
    int i = blockIdx.x * 256 + threadIdx.x;
    int stride = gridDim.x * 256;
    float4 z = {0.f, 0.f, 0.f, 0.f};
    float4* w4 = reinterpret_cast<float4*>(g_w);
    float4* d4 = reinterpret_cast<float4*>(g_den);
    for (int k = i; k < WTOT * 32; k += stride) w4[k] = z;
    for (int k = i; k < WTOT * 2;  k += stride) d4[k] = z;
    for (int k = i; k < WEXT;      k += stride) g_cnt[k] = 0;
    for (int k = i; k < 16384;     k += stride) {
        int f  = k & 15;
        int dd = (k >> 4) & 15;
        int h  = (k >> 8) & 7;
        int e  = k >> 11;
        g_msgT[e * 2048 + dd * 128 + h * 16 + f] = msg[k];
    }
}

// ---------------------------------------------------------------------------
// K1: histogram over expanded buckets (no-return atomicAdd -> REDG, cheap)
// ---------------------------------------------------------------------------
__global__ void hist_kernel(const int* __restrict__ edst)
{
    int idx = blockIdx.x * 256 + threadIdx.x;
    if (idx >= E_TOT) return;
    int e  = idx / E_PER;
    int sh = c_subsh[e];
    int bk = c_exoff[e] + (edst[idx] << sh) + (idx & ((1 << sh) - 1));
    atomicAdd(&g_cnt[bk], 1);
}

// ---------------------------------------------------------------------------
// K2: exclusive scan of g_cnt -> g_pos. Single block, 1024 thr x 128 each.
// ---------------------------------------------------------------------------
__global__ void __launch_bounds__(1024) scan_kernel()
{
    __shared__ int ss[1024];
    int t = threadIdx.x;
    int base = t * 128;
    int s = 0;
    for (int j = 0; j < 128; j++) {
        int idx = base + j;
        if (idx < WEXT) s += g_cnt[idx];
    }
    ss[t] = s;
    __syncthreads();
    for (int off = 1; off < 1024; off <<= 1) {
        int v = (t >= off) ? ss[t - off] : 0;
        __syncthreads();
        ss[t] += v;
        __syncthreads();
    }
    int run = ss[t] - s;   // exclusive prefix of this thread's chunk
    for (int j = 0; j < 128; j++) {
        int idx = base + j;
        if (idx < WEXT) {
            g_pos[idx] = run;
            run += g_cnt[idx];
        }
    }
}

// ---------------------------------------------------------------------------
// K3: scatter edges into (slot,sub)-sorted order. rec = (slot<<15)|src_global.
// Sub-buckets of a slot are contiguous, so slot-runs in g_rec stay contiguous
// (just internally partitioned; accum flushes partial runs anyway).
// ---------------------------------------------------------------------------
__global__ void scatter_kernel(const int* __restrict__ esrc,
                               const int* __restrict__ edst)
{
    int idx = blockIdx.x * 256 + threadIdx.x;
    if (idx >= E_TOT) return;
    int e  = idx / E_PER;
    int d  = edst[idx];
    int sh = c_subsh[e];
    int bk = c_exoff[e] + (d << sh) + (idx & ((1 << sh) - 1));
    unsigned slot = (unsigned)(c_woff[e] + d);
    unsigned sg   = (unsigned)(c_off[c_src_t[e]] + esrc[idx]);
    int pos = atomicAdd(&g_pos[bk], 1);
    g_rec[pos] = (slot << 15) | sg;
}

// ---------------------------------------------------------------------------
// K4: projections. block = 128 threads, 32 nodes per block.
// ---------------------------------------------------------------------------
__global__ void __launch_bounds__(128) proj_kernel(
    const float* __restrict__ xw, const float* __restrict__ xt,
    const float* __restrict__ xd,
    const float* __restrict__ Wk, const float* __restrict__ bk,
    const float* __restrict__ Wq, const float* __restrict__ bq,
    const float* __restrict__ Wv, const float* __restrict__ bv)
{
    int t  = blockIdx.z;
    int Nt = c_nt[t];
    int n0 = blockIdx.x * 32;
    if (n0 >= Nt) return;

    const float* x = (t == 0) ? xw : (t == 1) ? xt : xd;
    int m = blockIdx.y;
    const float* W = ((m == 0) ? Wk : (m == 1) ? Wq : Wv) + t * 256 * 128;
    const float* b = ((m == 0) ? bk : (m == 1) ? bq : bv) + t * 128;
    float* out = ((m == 0) ? g_k : (m == 1) ? g_q : g_v) + (size_t)(c_off[t] + n0) * 128;

    int j = threadIdx.x;

    unsigned long long acc2[16];
#pragma unroll
    for (int p = 0; p < 16; p++) acc2[p] = 0ull;

    __shared__ float xs[16][32];

    for (int kk = 0; kk < 256; kk += 16) {
        __syncthreads();
#pragma unroll
        for (int p = 0; p < 4; p++) {
            int idx = j + p * 128;
            int kc = idx >> 5, i = idx & 31;
            int n = n0 + i;
            xs[kc][i] = (n < Nt) ? x[(size_t)n * 256 + kk + kc] : 0.0f;
        }
        __syncthreads();
#pragma unroll
        for (int kc = 0; kc < 16; kc++) {
            float wv = W[(size_t)(kk + kc) * 128 + j];
            unsigned long long w2;
            asm("mov.b64 %0, {%1,%1};" : "=l"(w2) : "f"(wv));
#pragma unroll
            for (int p = 0; p < 16; p++) {
                unsigned long long xv =
                    *reinterpret_cast<const unsigned long long*>(&xs[kc][2 * p]);
                asm("fma.rn.f32x2 %0, %1, %2, %3;"
                    : "=l"(acc2[p]) : "l"(xv), "l"(w2), "l"(acc2[p]));
            }
        }
    }

    float bb = b[j];
#pragma unroll
    for (int p = 0; p < 16; p++) {
        float lo, hi;
        asm("mov.b64 {%0,%1}, %2;" : "=f"(lo), "=f"(hi) : "l"(acc2[p]));
        int n = n0 + 2 * p;
        if (n < Nt)     out[(size_t)(2 * p) * 128 + j]     = lo + bb;
        if (n + 1 < Nt) out[(size_t)(2 * p + 1) * 128 + j] = hi + bb;
    }
}

// ---------------------------------------------------------------------------
// K5: accumulation over the sorted edge stream. One warp per 64-edge chunk.
// ---------------------------------------------------------------------------
__global__ void __launch_bounds__(256) accum_kernel(const float* __restrict__ pri)
{
    int w = blockIdx.x * 8 + (threadIdx.x >> 5);
    if (w >= NCHUNK) return;
    int l = threadIdx.x & 31;
    int h = l >> 2;
    int i = w * CH;
    const int i1 = i + CH;
    unsigned rec = g_rec[i];

    for (;;) {
        unsigned slot = rec >> 15;
        int e = (slot >= 44150u) ? 7 : (slot >= 44100u) ? 6 : (slot >= 24100u) ? 5 :
                (slot >= 4100u)  ? 4 : (slot >= 4050u)  ? 3 : (slot >= 2050u)  ? 2 :
                (slot >= 50u)    ? 1 : 0;
        int dg = c_off[c_dst_t[e]] + (int)slot - c_woff[e];
        float4 q4 = *reinterpret_cast<const float4*>(g_q + (size_t)dg * 128 + 4 * l);
        float pr = pri[e * 8 + h] * 0.25f;

        float4 acc = make_float4(0.f, 0.f, 0.f, 0.f);
        float den = 0.f;
        bool last = false;

        for (;;) {
            unsigned sg = rec & 0x7FFFu;
            float4 k4 = *reinterpret_cast<const float4*>(g_k + (size_t)sg * 128 + 4 * l);
            float4 v4 = *reinterpret_cast<const float4*>(g_v + (size_t)sg * 128 + 4 * l);
            ++i;
            unsigned nrec = 0u;
            if (i < i1) nrec = g_rec[i];

            float p = q4.x * k4.x + q4.y * k4.y + q4.z * k4.z + q4.w * k4.w;
            p += __shfl_xor_sync(0xffffffffu, p, 1);
            p += __shfl_xor_sync(0xffffffffu, p, 2);
            float ex = __expf(p * pr);

            acc.x += ex * v4.x; acc.y += ex * v4.y;
            acc.z += ex * v4.z; acc.w += ex * v4.w;
            den += ex;

            if (i >= i1) { last = true; break; }
            rec = nrec;
            if ((rec >> 15) != slot) break;
        }

        float* wp = g_w + (size_t)slot * 128 + 4 * l;
        asm volatile("red.global.add.v4.f32 [%0], {%1,%2,%3,%4};"
                     :: "l"(wp), "f"(acc.x), "f"(acc.y), "f"(acc.z), "f"(acc.w)
                     : "memory");
        if ((l & 3) == 0)
            atomicAdd(&g_den[(size_t)slot * 8 + h], den);

        if (last) break;
    }
}

// ---------------------------------------------------------------------------
// K6: node epilogue. warp per node; lane l owns output cols [4l,4l+4).
// ---------------------------------------------------------------------------
__global__ void __launch_bounds__(256) out_kernel(
    const float* __restrict__ gamma, const float* __restrict__ beta,
    float* __restrict__ out)
{
    int n = blockIdx.x * 8 + (threadIdx.x >> 5);
    if (n >= NNODE) return;
    int l = threadIdx.x & 31;
    int h = l >> 2;
    int t = (n < 20000) ? 0 : (n < 20050) ? 1 : 2;
    int local = n - c_off[t];

    float4 acc = make_float4(0.f, 0.f, 0.f, 0.f);
#pragma unroll
    for (int ee = 0; ee < 3; ee++) {
        int e = c_t2e[t][ee];
        if (e >= 0) {   // warp-uniform (same node across warp)
            unsigned slot = (unsigned)(c_woff[e] + local);
            float den = g_den[(size_t)slot * 8 + h];
            float inv = (den > 0.f) ? (1.0f / den) : 0.f;  // branch-free, g_w zeroed
            float4 w4 = *reinterpret_cast<const float4*>(g_w + (size_t)slot * 128 + 4 * l);
            const float* mb = g_msgT + e * 2048 + h * 16 + (l & 3) * 4;
            float4 ea = make_float4(0.f, 0.f, 0.f, 0.f);
#pragma unroll
            for (int dd = 0; dd < 16; dd++) {
                float wc = ((dd & 3) == 0) ? w4.x : ((dd & 3) == 1) ? w4.y :
                           ((dd & 3) == 2) ? w4.z : w4.w;
                float wd = __shfl_sync(0xffffffffu, wc, (l & ~3) | (dd >> 2));
                float4 m4 = *reinterpret_cast<const float4*>(mb + dd * 128);
                ea.x += wd * m4.x; ea.y += wd * m4.y;
                ea.z += wd * m4.z; ea.w += wd * m4.w;
            }
            acc.x += inv * ea.x; acc.y += inv * ea.y;
            acc.z += inv * ea.z; acc.w += inv * ea.w;
        }
    }

    float ic = c_invcnt[t];
    float hv[4], s = 0.f, s2 = 0.f;
    float av[4] = {acc.x, acc.y, acc.z, acc.w};
#pragma unroll
    for (int j = 0; j < 4; j++) {
        float v = fmaxf(av[j] * ic, 0.f);
        hv[j] = v;
        s += v;
        s2 += v * v;
    }
#pragma unroll
    for (int o = 16; o >= 1; o >>= 1) {
        s  += __shfl_xor_sync(0xffffffffu, s,  o);
        s2 += __shfl_xor_sync(0xffffffffu, s2, o);
    }
    float mu   = s * (1.0f / 128.0f);
    float var  = s2 * (1.0f / 128.0f) - mu * mu;
    float rstd = rsqrtf(var + 1e-5f);
#pragma unroll
    for (int j = 0; j < 4; j++) {
        int col = 4 * l + j;
        out[(size_t)n * 128 + col] =
            (hv[j] - mu) * rstd * gamma[t * 128 + col] + beta[t * 128 + col];
    }
}

// ---------------------------------------------------------------------------
extern "C" void kernel_launch(void* const* d_in, const int* in_sizes, int n_in,
                              void* d_out, int out_size)
{
    const float* xw    = (const float*)d_in[0];
    const float* xt    = (const float*)d_in[1];
    const float* xd    = (const float*)d_in[2];
    const float* Wk    = (const float*)d_in[3];
    const float* bk    = (const float*)d_in[4];
    const float* Wq    = (const float*)d_in[5];
    const float* bq    = (const float*)d_in[6];
    const float* Wv    = (const float*)d_in[7];
    const float* bv    = (const float*)d_in[8];
    const float* pri   = (const float*)d_in[9];
    const float* msg   = (const float*)d_in[10];
    const float* gamma = (const float*)d_in[11];
    const float* beta  = (const float*)d_in[12];
    const int*   esrc  = (const int*)d_in[13];
    const int*   edst  = (const int*)d_in[14];
    float* out = (float*)d_out;

    int eblocks = (E_TOT + 255) / 256;

    zero_kernel<<<2048, 256>>>(msg);
    hist_kernel<<<eblocks, 256>>>(edst);
    scan_kernel<<<1, 1024>>>();
    scatter_kernel<<<eblocks, 256>>>(esrc, edst);
    dim3 gp(625, 3, 3);
    proj_kernel<<<gp, 128>>>(xw, xt, xd, Wk, bk, Wq, bq, Wv, bv);
    accum_kernel<<<(NCHUNK + 7) / 8, 256>>>(pri);
    out_kernel<<<(NNODE + 7) / 8, 256>>>(gamma, beta, out);
}